// round 2
// baseline (speedup 1.0000x reference)
#include <cuda_runtime.h>
#include <stdint.h>

namespace {

constexpr int WPB = 8;                  // warps (= images) per block
constexpr int THREADS = WPB * 32;

// Scale chain computed in double exactly like Python floats, cast to f32 at use.
constexpr double S0d = 0.05;
constexpr double C1d = S0d * 0.05;      // dequant mult after conv1
constexpr double S1d = C1d * 16.0;      // quant divisor before conv2
constexpr double C2d = S1d * 0.05;
constexpr double S2d = C2d * 16.0;
constexpr double C3d = S2d * 0.05;
constexpr double S3d = C3d * 16.0;
constexpr double C4d = S3d * 0.05;      // final dequant mult

// XLA rewrites x/const -> x * fl32(1/const). Precompute f32 reciprocals
// (constexpr float division is IEEE RNE, same as XLA's compile-time fold).
constexpr float S0F = (float)S0d;  constexpr float I0F = 1.0f / S0F;
constexpr float C1F = (float)C1d;  constexpr float I1F = 1.0f / (float)S1d;
constexpr float C2F = (float)C2d;  constexpr float I2F = 1.0f / (float)S2d;
constexpr float C3F = (float)C3d;  constexpr float I3F = 1.0f / (float)S3d;
constexpr float C4F = (float)C4d;

__device__ __forceinline__ int f2i(float f) { return __float2int_rn(f); }

__device__ __forceinline__ int pk(int a, int b, int c, int d) {
    return (a & 255) | ((b & 255) << 8) | ((c & 255) << 16) | ((d & 255) << 24);
}

// q = clip(round_half_even( fl(fl(m*C) * invS) ), -128, 127)
// __fmul_rn forbids FMA contraction — tie cases (m = 8 mod 16) depend on it.
__device__ __forceinline__ int quantize(int m, float C, float invS) {
    float y = __fmul_rn((float)m, C);
    float t = rintf(__fmul_rn(y, invS));
    t = fminf(fmaxf(t, -128.0f), 127.0f);
    return (int)t;
}

struct WS {
    uint8_t  qin[28 * 28];   // quantized input (values 0..20)
    uint32_t q2[13 * 13];    // layer-2 input, 4 channels packed per word
    uint8_t  q3[25 * 4];     // layer-3 input, [cell][ch], word-readable
    int      sacc[36];       // conv3 outputs (9 positions x 4 ch)
    uint32_t q4;             // layer-4 input, 4 channels packed
};

__global__ void __launch_bounds__(THREADS) qcnn_kernel(
    const float* __restrict__ x,
    const float* __restrict__ w1,
    const float* __restrict__ w2,
    const float* __restrict__ w3,
    const float* __restrict__ w4,
    float* __restrict__ out,
    int B)
{
    __shared__ WS ws[WPB];
    __shared__ int wp1[4][3];   // [oc][ky] : (w[ky,0],w[ky,1],w[ky,2],0) bytes
    __shared__ int wp2[4][9];   // [oc][ky*3+kx] : 4 in-channels packed
    __shared__ int wp3[4][9];
    __shared__ int wp4[12];     // [oc] : 4 in-channels packed

    const int tid = threadIdx.x;

    // ---- pack integer weights into dp4a operands (once per block) ----
    if (tid < 12) {
        int oc = tid / 3, ky = tid % 3;
        // w1 HWIO (3,3,4,4): idx = ((ky*3+kx)*4+ic)*4+oc ; ic=0, kx stride = 16
        const float* p = w1 + (ky * 3) * 16 + oc;
        wp1[oc][ky] = pk(f2i(p[0]), f2i(p[16]), f2i(p[32]), 0);
    } else if (tid < 48) {
        int j = tid - 12, oc = j / 9, k = j % 9;
        const float* p = w2 + k * 16 + oc;              // ic stride = 4 floats
        wp2[oc][k] = pk(f2i(p[0]), f2i(p[4]), f2i(p[8]), f2i(p[12]));
    } else if (tid < 84) {
        int j = tid - 48, oc = j / 9, k = j % 9;
        const float* p = w3 + k * 16 + oc;
        wp3[oc][k] = pk(f2i(p[0]), f2i(p[4]), f2i(p[8]), f2i(p[12]));
    } else if (tid < 96) {
        int oc = tid - 84;                               // w4 (1,1,4,12): ic*12+oc
        wp4[oc] = pk(f2i(w4[oc]), f2i(w4[12 + oc]), f2i(w4[24 + oc]), f2i(w4[36 + oc]));
    }
    __syncthreads();

    const int lane = tid & 31;
    const int wrp  = tid >> 5;
    const int img  = blockIdx.x * WPB + wrp;
    if (img >= B) return;
    WS& s = ws[wrp];

    // ---- stage 0: load + quantize input (28x28, ch0 only; ch1-3 are zero) ----
    {
        const float* xi = x + (size_t)img * 784;
        for (int i = lane; i < 784; i += 32) {
            float t = rintf(__fmul_rn(xi[i], I0F));
            t = fminf(fmaxf(t, -128.0f), 127.0f);
            s.qin[i] = (uint8_t)(int)t;
        }
    }
    __syncwarp();

    // ---- stage 1: conv1(3x3, 1->4) + maxpool2x2 + relu + quant -> q2[13][13] ----
    {
        for (int t = lane; t < 169; t += 32) {
            int py = t / 13, px = t % 13;
            const uint8_t* qp = s.qin + (2 * py) * 28 + 2 * px;
            uint32_t p0[4], p1[4];
            #pragma unroll
            for (int r = 0; r < 4; r++) {
                uint32_t b0 = qp[r * 28 + 0], b1 = qp[r * 28 + 1];
                uint32_t b2 = qp[r * 28 + 2], b3 = qp[r * 28 + 3];
                p0[r] = b0 | (b1 << 8) | (b2 << 16) | (b3 << 24);
                p1[r] = __byte_perm(p0[r], 0, 0x4321);   // (b1,b2,b3,0)
            }
            uint32_t ow = 0;
            #pragma unroll
            for (int oc = 0; oc < 4; oc++) {
                int k0 = wp1[oc][0], k1 = wp1[oc][1], k2 = wp1[oc][2];
                int a00 = __dp4a((int)p0[0], k0, __dp4a((int)p0[1], k1, __dp4a((int)p0[2], k2, 0)));
                int a01 = __dp4a((int)p1[0], k0, __dp4a((int)p1[1], k1, __dp4a((int)p1[2], k2, 0)));
                int a10 = __dp4a((int)p0[1], k0, __dp4a((int)p0[2], k1, __dp4a((int)p0[3], k2, 0)));
                int a11 = __dp4a((int)p1[1], k0, __dp4a((int)p1[2], k1, __dp4a((int)p1[3], k2, 0)));
                int m = max(max(a00, a01), max(a10, a11));
                m = max(m, 0);
                ow |= (uint32_t)quantize(m, C1F, I1F) << (8 * oc);
            }
            s.q2[t] = ow;
        }
    }
    __syncwarp();

    // ---- stage 2: conv2(3x3, 4->4) + maxpool2x2 + relu + quant -> q3[25][4] ----
    {
        for (int t = lane; t < 100; t += 32) {
            int cell = t >> 2, oc = t & 3;
            int py = cell / 5, px = cell % 5;
            const uint32_t* q2 = s.q2 + (2 * py) * 13 + 2 * px;
            uint32_t rw[16];
            #pragma unroll
            for (int r = 0; r < 4; r++)
                #pragma unroll
                for (int c = 0; c < 4; c++)
                    rw[r * 4 + c] = q2[r * 13 + c];
            const int* wo = wp2[oc];
            int m = 0;
            bool first = true;
            #pragma unroll
            for (int dy = 0; dy < 2; dy++)
                #pragma unroll
                for (int dx = 0; dx < 2; dx++) {
                    int a = 0;
                    #pragma unroll
                    for (int ky = 0; ky < 3; ky++)
                        #pragma unroll
                        for (int kx = 0; kx < 3; kx++)
                            a = __dp4a((int)rw[(dy + ky) * 4 + dx + kx], wo[ky * 3 + kx], a);
                    m = first ? a : max(m, a);
                    first = false;
                }
            m = max(m, 0);  // relu
            s.q3[cell * 4 + oc] = (uint8_t)quantize(m, C2F, I2F);
        }
    }
    __syncwarp();

    // ---- stage 3: conv3(3x3, 4->4) -> 3x3, then maxpool3x3 + relu + quant -> q4 ----
    {
        for (int t = lane; t < 36; t += 32) {
            int pos = t >> 2, oc = t & 3;
            int py = pos / 3, px = pos % 3;
            const uint32_t* q3w = (const uint32_t*)s.q3;
            const int* wo = wp3[oc];
            int a = 0;
            #pragma unroll
            for (int ky = 0; ky < 3; ky++)
                #pragma unroll
                for (int kx = 0; kx < 3; kx++)
                    a = __dp4a((int)q3w[(py + ky) * 5 + px + kx], wo[ky * 3 + kx], a);
            s.sacc[t] = a;
        }
        __syncwarp();
        if (lane < 4) {
            int oc = lane;
            int m = s.sacc[oc];
            #pragma unroll
            for (int p = 1; p < 9; p++) m = max(m, s.sacc[p * 4 + oc]);
            m = max(m, 0);  // relu
            ((uint8_t*)&s.q4)[oc] = (uint8_t)quantize(m, C3F, I3F);
        }
    }
    __syncwarp();

    // ---- stage 4: conv4(1x1, 4->12) + relu; emit first 10 channels ----
    {
        if (lane < 10) {
            int a = __dp4a((int)s.q4, wp4[lane], 0);
            float y = fmaxf(__fmul_rn((float)a, C4F), 0.0f);
            out[(size_t)img * 10 + lane] = y;
        }
    }
}

} // namespace

extern "C" void kernel_launch(void* const* d_in, const int* in_sizes, int n_in,
                              void* d_out, int out_size) {
    const float* x  = (const float*)d_in[0];
    const float* w1 = (const float*)d_in[1];
    const float* w2 = (const float*)d_in[2];
    const float* w3 = (const float*)d_in[3];
    const float* w4 = (const float*)d_in[4];
    float* out = (float*)d_out;

    int B = in_sizes[0] / 784;
    int blocks = (B + WPB - 1) / WPB;
    qcnn_kernel<<<blocks, THREADS>>>(x, w1, w2, w3, w4, out, B);
}

// round 7
// speedup vs baseline: 1.0501x; 1.0501x over previous
#include <cuda_runtime.h>
#include <stdint.h>

namespace {

constexpr int WPB = 8;                  // warps (= images) per block
constexpr int THREADS = WPB * 32;

// Scale chain in double exactly like Python floats, cast to f32 at use.
constexpr double S0d = 0.05;
constexpr double C1d = S0d * 0.05;
constexpr double S1d = C1d * 16.0;
constexpr double C2d = S1d * 0.05;
constexpr double S2d = C2d * 16.0;
constexpr double C3d = S2d * 0.05;
constexpr double S3d = C3d * 16.0;
constexpr double C4d = S3d * 0.05;

// XLA rewrites x/const -> x * fl32(1/const)
constexpr float I0F = 1.0f / (float)S0d;
constexpr float C1F = (float)C1d;  constexpr float I1F = 1.0f / (float)S1d;
constexpr float C2F = (float)C2d;  constexpr float I2F = 1.0f / (float)S2d;
constexpr float C3F = (float)C3d;  constexpr float I3F = 1.0f / (float)S3d;
constexpr float C4F = (float)C4d;

__device__ __forceinline__ int f2i(float f) { return __float2int_rn(f); }

__device__ __forceinline__ int pk(int a, int b, int c, int d) {
    return (a & 255) | ((b & 255) << 8) | ((c & 255) << 16) | ((d & 255) << 24);
}

// Layer-1 quantize: bounds proven (0 <= m <= 1440 -> 0 <= q <= 90), no clamp.
// __fmul_rn forbids FMA contraction; two multiplies must match XLA exactly.
__device__ __forceinline__ int qnc(int m, float C, float I) {
    return __float2int_rn(__fmul_rn(__fmul_rn(__int2float_rn(m), C), I));
}
// Clamped quantize (m >= 0 post-relu, so only the upper clip can bind).
// clip(round(z)) == round(clip(z)) for integer bounds.
__device__ __forceinline__ int qcl(int m, float C, float I) {
    float z = __fmul_rn(__fmul_rn(__int2float_rn(m), C), I);
    return __float2int_rn(fminf(z, 127.0f));
}

// (a.b0, b.b0, c.b0, d.b0) -> one word. Selector nibbles are LSB-first:
// 0x0040: byte0 = src_a.b0 (nib 0), byte1 = src_b.b0 (nib 4).
__device__ __forceinline__ uint32_t pack4(int a, int b, int c, int d) {
    return __byte_perm(__byte_perm(a, b, 0x0040), __byte_perm(c, d, 0x0040), 0x5410);
}

struct __align__(16) WS {
    uint32_t qin[28 * 8];    // 28 rows x 32B (7 data words + 1 pad word)
    uint32_t q2[13 * 14];    // 13 rows, stride 14 words (even => 8B-aligned reads)
    uint32_t q3[26];         // 5x5 cells, 4 ch packed per word (+pad)
};

__global__ void __launch_bounds__(THREADS) qcnn_kernel(
    const float* __restrict__ x,
    const float* __restrict__ w1,
    const float* __restrict__ w2,
    const float* __restrict__ w3,
    const float* __restrict__ w4,
    float* __restrict__ out,
    int B)
{
    __shared__ WS ws[WPB];
    __shared__ int wp1[4][3];   // [oc][ky]: (w[ky,0],w[ky,1],w[ky,2],0)
    __shared__ int wp2[4][9];   // [oc][ky*3+kx]: 4 in-ch packed
    __shared__ int wp3[4][9];
    __shared__ int wp4[12];

    const int tid = threadIdx.x;

    // ---- pack integer weights into dp4a operands (once per block) ----
    if (tid < 12) {
        int oc = tid / 3, ky = tid % 3;
        const float* p = w1 + (ky * 3) * 16 + oc;     // HWIO, ic=0, kx stride 16
        wp1[oc][ky] = pk(f2i(p[0]), f2i(p[16]), f2i(p[32]), 0);
    } else if (tid < 48) {
        int j = tid - 12, oc = j / 9, k = j % 9;
        const float* p = w2 + k * 16 + oc;
        wp2[oc][k] = pk(f2i(p[0]), f2i(p[4]), f2i(p[8]), f2i(p[12]));
    } else if (tid < 84) {
        int j = tid - 48, oc = j / 9, k = j % 9;
        const float* p = w3 + k * 16 + oc;
        wp3[oc][k] = pk(f2i(p[0]), f2i(p[4]), f2i(p[8]), f2i(p[12]));
    } else if (tid < 96) {
        int oc = tid - 84;
        wp4[oc] = pk(f2i(w4[oc]), f2i(w4[12 + oc]), f2i(w4[24 + oc]), f2i(w4[36 + oc]));
    }
    __syncthreads();

    const int lane = tid & 31;
    const int wrp  = tid >> 5;
    const int img  = blockIdx.x * WPB + wrp;
    if (img >= B) return;
    WS& s = ws[wrp];

    // ---- stage 0: quantize input; pack 4 px/word. x in [0,1) => q in [0,20], no clamp ----
    {
        const float4* xi4 = (const float4*)(x + (size_t)img * 784);
        for (int g = lane; g < 196; g += 32) {           // group g: row g/7, word g%7
            float4 v = xi4[g];
            int a = __float2int_rn(__fmul_rn(v.x, I0F));
            int b = __float2int_rn(__fmul_rn(v.y, I0F));
            int c = __float2int_rn(__fmul_rn(v.z, I0F));
            int d = __float2int_rn(__fmul_rn(v.w, I0F));
            int row = g / 7, word = g - row * 7;
            s.qin[row * 8 + word] = pack4(a, b, c, d);
        }
    }
    __syncwarp();

    // ---- stage 1: conv1(3x3,1->4) + maxpool2x2 + relu + quant -> q2[13][13] ----
    {
        for (int t = lane; t < 169; t += 32) {
            int py = t / 13, px = t - py * 13;
            int base = (2 * py) * 8 + (px >> 1);         // word of byte 2*px
            unsigned sel = (px & 1) ? 0x5432u : 0x3210u; // extract bytes 2px..2px+3
            uint32_t p0[4], p1[4];
            #pragma unroll
            for (int r = 0; r < 4; r++) {
                uint32_t wa = s.qin[base + r * 8];
                uint32_t wb = s.qin[base + r * 8 + 1];
                p0[r] = __byte_perm(wa, wb, sel);
                p1[r] = __byte_perm(p0[r], 0, 0x4321);
            }
            int q[4];
            #pragma unroll
            for (int oc = 0; oc < 4; oc++) {
                int k0 = wp1[oc][0], k1 = wp1[oc][1], k2 = wp1[oc][2];
                int a00 = __dp4a((int)p0[0], k0, __dp4a((int)p0[1], k1, __dp4a((int)p0[2], k2, 0)));
                int a01 = __dp4a((int)p1[0], k0, __dp4a((int)p1[1], k1, __dp4a((int)p1[2], k2, 0)));
                int a10 = __dp4a((int)p0[1], k0, __dp4a((int)p0[2], k1, __dp4a((int)p0[3], k2, 0)));
                int a11 = __dp4a((int)p1[1], k0, __dp4a((int)p1[2], k1, __dp4a((int)p1[3], k2, 0)));
                int m = max(max(max(a00, a01), max(a10, a11)), 0);
                q[oc] = qnc(m, C1F, I1F);
            }
            s.q2[py * 14 + px] = pack4(q[0], q[1], q[2], q[3]);
        }
    }
    __syncwarp();

    // ---- stage 2: conv2(3x3,4->4) + maxpool2x2 + relu + quant -> q3[25] ----
    if (lane < 25) {
        int py = lane / 5, px = lane - py * 5;
        const uint2* qb = (const uint2*)(s.q2 + (2 * py) * 14 + 2 * px);
        uint32_t rw[4][4];
        #pragma unroll
        for (int r = 0; r < 4; r++) {
            uint2 a = qb[r * 7], b = qb[r * 7 + 1];
            rw[r][0] = a.x; rw[r][1] = a.y; rw[r][2] = b.x; rw[r][3] = b.y;
        }
        int q[4];
        #pragma unroll
        for (int oc = 0; oc < 4; oc++) {
            const int* wo = wp2[oc];
            int m = 0; bool first = true;
            #pragma unroll
            for (int dy = 0; dy < 2; dy++)
                #pragma unroll
                for (int dx = 0; dx < 2; dx++) {
                    int a = 0;
                    #pragma unroll
                    for (int ky = 0; ky < 3; ky++)
                        #pragma unroll
                        for (int kx = 0; kx < 3; kx++)
                            a = __dp4a((int)rw[dy + ky][dx + kx], wo[ky * 3 + kx], a);
                    m = first ? a : max(m, a); first = false;
                }
            m = max(m, 0);
            q[oc] = qcl(m, C2F, I2F);
        }
        s.q3[lane] = pack4(q[0], q[1], q[2], q[3]);
    }
    __syncwarp();

    // ---- stage 3: conv3(3x3,4->4) -> 3x3, pool3x3 + relu + quant (shuffle reduce) ----
    int acc0 = 0, acc1 = 0, acc2 = 0, acc3 = 0;   // zeros = relu floor on idle lanes
    if (lane < 9) {
        int py = lane / 3, px = lane - py * 3;
        uint32_t v[9];
        #pragma unroll
        for (int ky = 0; ky < 3; ky++)
            #pragma unroll
            for (int kx = 0; kx < 3; kx++)
                v[ky * 3 + kx] = s.q3[(py + ky) * 5 + px + kx];
        #pragma unroll
        for (int k = 0; k < 9; k++) {
            acc0 = __dp4a((int)v[k], wp3[0][k], acc0);
            acc1 = __dp4a((int)v[k], wp3[1][k], acc1);
            acc2 = __dp4a((int)v[k], wp3[2][k], acc2);
            acc3 = __dp4a((int)v[k], wp3[3][k], acc3);
        }
    }
    #pragma unroll
    for (int off = 8; off > 0; off >>= 1) {
        acc0 = max(acc0, __shfl_xor_sync(0xFFFFFFFFu, acc0, off));
        acc1 = max(acc1, __shfl_xor_sync(0xFFFFFFFFu, acc1, off));
        acc2 = max(acc2, __shfl_xor_sync(0xFFFFFFFFu, acc2, off));
        acc3 = max(acc3, __shfl_xor_sync(0xFFFFFFFFu, acc3, off));
    }
    // lanes 0..15 now hold pooled+relu'd maxima; quantize redundantly (uniform)
    int q4w = (int)pack4(qcl(acc0, C3F, I3F), qcl(acc1, C3F, I3F),
                         qcl(acc2, C3F, I3F), qcl(acc3, C3F, I3F));

    // ---- stage 4: conv4(1x1,4->12) + relu; emit channels 0..9 ----
    if (lane < 10) {
        int a = __dp4a(q4w, wp4[lane], 0);
        out[(size_t)img * 10 + lane] = fmaxf(__fmul_rn(__int2float_rn(a), C4F), 0.0f);
    }
}

} // namespace

extern "C" void kernel_launch(void* const* d_in, const int* in_sizes, int n_in,
                              void* d_out, int out_size) {
    const float* x  = (const float*)d_in[0];
    const float* w1 = (const float*)d_in[1];
    const float* w2 = (const float*)d_in[2];
    const float* w3 = (const float*)d_in[3];
    const float* w4 = (const float*)d_in[4];
    float* out = (float*)d_out;

    int B = in_sizes[0] / 784;
    int blocks = (B + WPB - 1) / WPB;
    qcnn_kernel<<<blocks, THREADS>>>(x, w1, w2, w3, w4, out, B);
}

// round 8
// speedup vs baseline: 1.0941x; 1.0419x over previous
#include <cuda_runtime.h>
#include <stdint.h>

namespace {

constexpr int WPB = 4;                  // warps (= images) per block
constexpr int THREADS = WPB * 32;

// Scale chain in double exactly like Python floats, cast to f32 at use.
constexpr double S0d = 0.05;
constexpr double C1d = S0d * 0.05;
constexpr double S1d = C1d * 16.0;
constexpr double C2d = S1d * 0.05;
constexpr double S2d = C2d * 16.0;
constexpr double C3d = S2d * 0.05;
constexpr double S3d = C3d * 16.0;
constexpr double C4d = S3d * 0.05;

// XLA rewrites x/const -> x * fl32(1/const)
constexpr float I0F = 1.0f / (float)S0d;
constexpr float C1F = (float)C1d;  constexpr float I1F = 1.0f / (float)S1d;
constexpr float C2F = (float)C2d;  constexpr float I2F = 1.0f / (float)S2d;
constexpr float C3F = (float)C3d;  constexpr float I3F = 1.0f / (float)S3d;
constexpr float C4F = (float)C4d;

__device__ __forceinline__ int f2i(float f) { return __float2int_rn(f); }

__device__ __forceinline__ int pk(int a, int b, int c, int d) {
    return (a & 255) | ((b & 255) << 8) | ((c & 255) << 16) | ((d & 255) << 24);
}

// Layer-1 quantize: bounds proven (0 <= m <= 1440 -> 0 <= q <= 90), no clamp.
// __fmul_rn forbids FMA contraction; two multiplies must match XLA exactly.
__device__ __forceinline__ int qnc(int m, float C, float I) {
    return __float2int_rn(__fmul_rn(__fmul_rn(__int2float_rn(m), C), I));
}
// Clamped quantize (m >= 0 post-relu, so only the upper clip can bind).
__device__ __forceinline__ int qcl(int m, float C, float I) {
    float z = __fmul_rn(__fmul_rn(__int2float_rn(m), C), I);
    return __float2int_rn(fminf(z, 127.0f));
}

// (a.b0, b.b0, c.b0, d.b0) -> one word. Selector nibbles LSB-first.
__device__ __forceinline__ uint32_t pack4(int a, int b, int c, int d) {
    return __byte_perm(__byte_perm(a, b, 0x0040), __byte_perm(c, d, 0x0040), 0x5410);
}

struct __align__(16) WS {
    uint32_t qin[198];       // 28 rows x 7 words, contiguous (+2 pad: OOB guard + 8B align)
    uint32_t q2[13 * 14];    // 13 rows, stride 14 words (even => 8B-aligned uint2 reads)
    uint32_t q3[26];         // 5x5 cells, 4 ch packed per word (+pad)
};

__global__ void __launch_bounds__(THREADS, 12) qcnn_kernel(
    const float* __restrict__ x,
    const float* __restrict__ w1,
    const float* __restrict__ w2,
    const float* __restrict__ w3,
    const float* __restrict__ w4,
    float* __restrict__ out,
    int B)
{
    __shared__ WS ws[WPB];
    __shared__ int wp1[4][3];   // [oc][ky]: (w[ky,0],w[ky,1],w[ky,2],0)
    __shared__ int wp2[4][9];   // [oc][ky*3+kx]: 4 in-ch packed
    __shared__ int wp3[4][9];
    __shared__ int wp4[12];

    const int tid = threadIdx.x;

    // ---- pack integer weights into dp4a operands (once per block) ----
    if (tid < 12) {
        int oc = tid / 3, ky = tid % 3;
        const float* p = w1 + (ky * 3) * 16 + oc;     // HWIO, ic=0, kx stride 16
        wp1[oc][ky] = pk(f2i(p[0]), f2i(p[16]), f2i(p[32]), 0);
    } else if (tid < 48) {
        int j = tid - 12, oc = j / 9, k = j % 9;
        const float* p = w2 + k * 16 + oc;
        wp2[oc][k] = pk(f2i(p[0]), f2i(p[4]), f2i(p[8]), f2i(p[12]));
    } else if (tid < 84) {
        int j = tid - 48, oc = j / 9, k = j % 9;
        const float* p = w3 + k * 16 + oc;
        wp3[oc][k] = pk(f2i(p[0]), f2i(p[4]), f2i(p[8]), f2i(p[12]));
    } else if (tid < 96) {
        int oc = tid - 84;
        wp4[oc] = pk(f2i(w4[oc]), f2i(w4[12 + oc]), f2i(w4[24 + oc]), f2i(w4[36 + oc]));
    }
    __syncthreads();

    const int lane = tid & 31;
    const int wrp  = tid >> 5;
    const int img  = blockIdx.x * WPB + wrp;
    if (img >= B) return;
    WS& s = ws[wrp];

    // ---- stage 0: quantize input; pack 4 px/word (contiguous, no row pad) ----
    {
        const float4* xi4 = (const float4*)(x + (size_t)img * 784);
        for (int g = lane; g < 196; g += 32) {
            float4 v = xi4[g];
            int a = __float2int_rn(__fmul_rn(v.x, I0F));
            int b = __float2int_rn(__fmul_rn(v.y, I0F));
            int c = __float2int_rn(__fmul_rn(v.z, I0F));
            int d = __float2int_rn(__fmul_rn(v.w, I0F));
            s.qin[g] = pack4(a, b, c, d);
        }
    }
    __syncwarp();

    // ---- stage 1: conv1(3x3,1->4) + maxpool2x2 + relu + quant -> q2[13][13] ----
    {
        for (int t = lane; t < 169; t += 32) {
            int py = t / 13, px = t - py * 13;
            int base = py * 14 + (px >> 1);              // (2py)*7 + px/2
            unsigned sel = (px & 1) ? 0x5432u : 0x3210u; // bytes 2px..2px+3 of row
            uint32_t p0[4], p1[4];
            #pragma unroll
            for (int r = 0; r < 4; r++) {
                uint32_t wa = s.qin[base + r * 7];
                uint32_t wb = s.qin[base + r * 7 + 1];
                p0[r] = __byte_perm(wa, wb, sel);
                p1[r] = __byte_perm(p0[r], 0, 0x4321);
            }
            int q[4];
            #pragma unroll
            for (int oc = 0; oc < 4; oc++) {
                int k0 = wp1[oc][0], k1 = wp1[oc][1], k2 = wp1[oc][2];
                int a00 = __dp4a((int)p0[0], k0, __dp4a((int)p0[1], k1, __dp4a((int)p0[2], k2, 0)));
                int a01 = __dp4a((int)p1[0], k0, __dp4a((int)p1[1], k1, __dp4a((int)p1[2], k2, 0)));
                int a10 = __dp4a((int)p0[1], k0, __dp4a((int)p0[2], k1, __dp4a((int)p0[3], k2, 0)));
                int a11 = __dp4a((int)p1[1], k0, __dp4a((int)p1[2], k1, __dp4a((int)p1[3], k2, 0)));
                int m = max(max(max(a00, a01), max(a10, a11)), 0);
                q[oc] = qnc(m, C1F, I1F);
            }
            s.q2[py * 14 + px] = pack4(q[0], q[1], q[2], q[3]);
        }
    }
    __syncwarp();

    // ---- stage 2: conv2(3x3,4->4) + maxpool2x2 + relu + quant -> q3[25] ----
    if (lane < 25) {
        int py = lane / 5, px = lane - py * 5;
        const uint2* qb = (const uint2*)(s.q2 + (2 * py) * 14 + 2 * px);
        uint32_t rw[4][4];
        #pragma unroll
        for (int r = 0; r < 4; r++) {
            uint2 a = qb[r * 7], b = qb[r * 7 + 1];
            rw[r][0] = a.x; rw[r][1] = a.y; rw[r][2] = b.x; rw[r][3] = b.y;
        }
        int q[4];
        #pragma unroll
        for (int oc = 0; oc < 4; oc++) {
            const int* wo = wp2[oc];
            int m = 0; bool first = true;
            #pragma unroll
            for (int dy = 0; dy < 2; dy++)
                #pragma unroll
                for (int dx = 0; dx < 2; dx++) {
                    int a = 0;
                    #pragma unroll
                    for (int ky = 0; ky < 3; ky++)
                        #pragma unroll
                        for (int kx = 0; kx < 3; kx++)
                            a = __dp4a((int)rw[dy + ky][dx + kx], wo[ky * 3 + kx], a);
                    m = first ? a : max(m, a); first = false;
                }
            m = max(m, 0);
            q[oc] = qcl(m, C2F, I2F);
        }
        s.q3[lane] = pack4(q[0], q[1], q[2], q[3]);
    }
    __syncwarp();

    // ---- stage 3: conv3(3x3,4->4) -> 3x3, pool3x3 + relu + quant (shuffle reduce) ----
    int acc0 = 0, acc1 = 0, acc2 = 0, acc3 = 0;   // zeros = relu floor on idle lanes
    if (lane < 9) {
        int py = lane / 3, px = lane - py * 3;
        uint32_t v[9];
        #pragma unroll
        for (int ky = 0; ky < 3; ky++)
            #pragma unroll
            for (int kx = 0; kx < 3; kx++)
                v[ky * 3 + kx] = s.q3[(py + ky) * 5 + px + kx];
        #pragma unroll
        for (int k = 0; k < 9; k++) {
            acc0 = __dp4a((int)v[k], wp3[0][k], acc0);
            acc1 = __dp4a((int)v[k], wp3[1][k], acc1);
            acc2 = __dp4a((int)v[k], wp3[2][k], acc2);
            acc3 = __dp4a((int)v[k], wp3[3][k], acc3);
        }
    }
    #pragma unroll
    for (int off = 8; off > 0; off >>= 1) {
        acc0 = max(acc0, __shfl_xor_sync(0xFFFFFFFFu, acc0, off));
        acc1 = max(acc1, __shfl_xor_sync(0xFFFFFFFFu, acc1, off));
        acc2 = max(acc2, __shfl_xor_sync(0xFFFFFFFFu, acc2, off));
        acc3 = max(acc3, __shfl_xor_sync(0xFFFFFFFFu, acc3, off));
    }
    int q4w = (int)pack4(qcl(acc0, C3F, I3F), qcl(acc1, C3F, I3F),
                         qcl(acc2, C3F, I3F), qcl(acc3, C3F, I3F));

    // ---- stage 4: conv4(1x1,4->12) + relu; emit channels 0..9 ----
    if (lane < 10) {
        int a = __dp4a(q4w, wp4[lane], 0);
        out[(size_t)img * 10 + lane] = fmaxf(__fmul_rn(__int2float_rn(a), C4F), 0.0f);
    }
}

} // namespace

extern "C" void kernel_launch(void* const* d_in, const int* in_sizes, int n_in,
                              void* d_out, int out_size) {
    const float* x  = (const float*)d_in[0];
    const float* w1 = (const float*)d_in[1];
    const float* w2 = (const float*)d_in[2];
    const float* w3 = (const float*)d_in[3];
    const float* w4 = (const float*)d_in[4];
    float* out = (float*)d_out;

    int B = in_sizes[0] / 784;
    int blocks = (B + WPB - 1) / WPB;
    qcnn_kernel<<<blocks, THREADS>>>(x, w1, w2, w3, w4, out, B);
}